// round 17
// baseline (speedup 1.0000x reference)
#include <cuda_runtime.h>
#include <cuda_bf16.h>

// ROI pooling (crop + 7x7 bilinear resize), NHWC.
// img:  (1, 128, 128, 1024) fp32
// rois: (1, 1000, 4) int32  -> {x, y, w, h}
// out:  (1, 1000, 7, 7, 1024) fp32
//
// Champion body (precomputed per-px offsets + 4 weights, depth-1 LDG.128
// lookahead, __stcs) at single-warp CTA granularity: 32-thread CTAs,
// 1-D grid with channel-EIGHTH in the low 3 bits, so 8 consecutive
// (co-scheduled) CTAs write one contiguous 28KB span and read the same
// two image rows.

#define H_IMG 128
#define W_IMG 128
#define C_IMG 1024
#define POOL 7
#define NUM_ROIS 1000
#define CPP (C_IMG / 4)   // float4s per pixel = 256

__global__ __launch_bounds__(32, 32)
void roi_pool_kernel(const float* __restrict__ img,
                     const int*   __restrict__ rois,
                     float*       __restrict__ out)
{
    const int bid    = blockIdx.x;          // 0 .. 55999
    const int eighth = bid & 7;             // channel eighth (low bits)
    const int b      = bid >> 3;            // (roi, py) index, 0..6999
    const int py = b % POOL;
    const int r  = b / POOL;
    const int c4 = threadIdx.x + (eighth << 5);   // 0..255 float4 channel

    const int4 roi = __ldg(((const int4*)rois) + r);
    const int rx = roi.x, ry = roi.y, rw = roi.z, rh = roi.w;

    // y axis (uniform across CTA)
    const float hf = (float)rh;
    float fy = (py + 0.5f) * (hf * (1.0f / POOL)) - 0.5f;
    fy = fminf(fmaxf(fy, 0.0f), fmaxf(hf - 1.0f, 0.0f));
    int   iy0 = (int)floorf(fy);
    const float wy  = fy - (float)iy0;
    const float wy1 = 1.0f - wy;
    int   iy1 = min(iy0 + 1, rh - 1);
    iy0 += ry;  iy1 += ry;

    const float4* __restrict__ row0 =
        (const float4*)(img + ((size_t)iy0 * W_IMG) * C_IMG) + c4;
    const float4* __restrict__ row1 =
        (const float4*)(img + ((size_t)iy1 * W_IMG) * C_IMG) + c4;

    // x axis scalars (uniform)
    const float wf  = (float)rw;
    const float sfx = wf * (1.0f / POOL);
    const float xcl = fmaxf(wf - 1.0f, 0.0f);

    // Precompute per-px column offsets and the 4 bilinear weights (all uniform).
    int   o0[POOL], o1[POOL];
    float w00[POOL], w01[POOL], w10[POOL], w11[POOL];
    #pragma unroll
    for (int px = 0; px < POOL; ++px) {
        float fx = (px + 0.5f) * sfx - 0.5f;
        fx = fminf(fmaxf(fx, 0.0f), xcl);
        int   ix0 = (int)floorf(fx);
        const float wx  = fx - (float)ix0;
        const float wx1 = 1.0f - wx;
        int   ix1 = min(ix0 + 1, rw - 1);
        o0[px] = (rx + ix0) * CPP;
        o1[px] = (rx + ix1) * CPP;
        w00[px] = wx1 * wy1;
        w01[px] = wx  * wy1;
        w10[px] = wx1 * wy;
        w11[px] = wx  * wy;
    }

    float4* __restrict__ optr =
        (float4*)out + ((size_t)(r * POOL + py) * POOL) * CPP + c4;

    // Software-pipelined px loop: loads for px+1 issue before math of px.
    float4 v00 = __ldg(row0 + o0[0]);
    float4 v01 = __ldg(row0 + o1[0]);
    float4 v10 = __ldg(row1 + o0[0]);
    float4 v11 = __ldg(row1 + o1[0]);

    #pragma unroll
    for (int px = 0; px < POOL; ++px) {
        float4 n00, n01, n10, n11;
        if (px + 1 < POOL) {
            const int p0 = o0[px + 1], p1 = o1[px + 1];
            n00 = __ldg(row0 + p0);
            n01 = __ldg(row0 + p1);
            n10 = __ldg(row1 + p0);
            n11 = __ldg(row1 + p1);
        }

        const float a = w00[px], bb = w01[px];
        const float c = w10[px], d  = w11[px];
        float4 o;
        o.x = v00.x * a + v01.x * bb + v10.x * c + v11.x * d;
        o.y = v00.y * a + v01.y * bb + v10.y * c + v11.y * d;
        o.z = v00.z * a + v01.z * bb + v10.z * c + v11.z * d;
        o.w = v00.w * a + v01.w * bb + v10.w * c + v11.w * d;

        __stcs(optr + (size_t)px * CPP, o);

        v00 = n00; v01 = n01; v10 = n10; v11 = n11;
    }
}

extern "C" void kernel_launch(void* const* d_in, const int* in_sizes, int n_in,
                              void* d_out, int out_size)
{
    const float* img  = (const float*)d_in[0];
    const int*   rois = (const int*)d_in[1];
    float*       out  = (float*)d_out;

    dim3 grid(NUM_ROIS * POOL * 8);
    dim3 block(32);
    roi_pool_kernel<<<grid, block>>>(img, rois, out);
}